// round 3
// baseline (speedup 1.0000x reference)
#include <cuda_runtime.h>
#include <cstdint>

typedef unsigned long long ull;

// Packed fp32x2 FMA (sm_100+; ptxas never emits this from plain C++).
__device__ __forceinline__ ull fma2(ull a, ull b, ull c) {
    ull d;
    asm("fma.rn.f32x2 %0, %1, %2, %3;" : "=l"(d) : "l"(a), "l"(b), "l"(c));
    return d;
}
__device__ __forceinline__ ull dup2(float x) {
    ull d;
    asm("mov.b64 %0, {%1, %1};" : "=l"(d) : "f"(x));
    return d;
}
__device__ __forceinline__ void unpack2(ull v, float& lo, float& hi) {
    asm("mov.b64 {%0, %1}, %2;" : "=f"(lo), "=f"(hi) : "l"(v));
}
__device__ __forceinline__ ull pack2(float lo, float hi) {
    ull d;
    asm("mov.b64 %0, {%1, %2};" : "=l"(d) : "f"(lo), "f"(hi));
    return d;
}

// b0[r,f,n] = sum_m CG0[r,m]*A[f,m,n]  (r=0..7)
// b1[r,f,n] = sum_m CG1[r,m]*A[f,m,n]  (r=0..23)
// Accumulators packed along r (pairs of adjacent r), CG stored transposed
// [m][r] in shared so multiplier pairs load packed with zero duplication.
template <int M, int F>
__global__ void __launch_bounds__(256, 2)
sym_kernel(const float* __restrict__ A,
           const float* __restrict__ cg0,
           const float* __restrict__ cg1,
           float* __restrict__ out0,
           float* __restrict__ out1) {
    __shared__ __align__(16) float cgs[M][32];   // [m][r], r contiguous
    const int tid = threadIdx.x;
    for (int i = tid; i < M * 32; i += 256) {
        const int mi = i >> 5;
        const int r = i & 31;
        cgs[mi][r] = (r < 8) ? cg0[r * M + mi] : cg1[(r - 8) * M + mi];
    }
    __syncthreads();

    const int f = blockIdx.x;
    const int n0 = blockIdx.y * 512 + tid * 2;   // even, <= 1022
    const float* aptr = A + (size_t)f * (M * 1024) + n0;

    // acc[p][j]: packed (b[2p], b[2p+1]) at column n0+j
    ull acc[16][2];
#pragma unroll
    for (int p = 0; p < 16; p++) { acc[p][0] = 0ull; acc[p][1] = 0ull; }

    float2 a_next = *reinterpret_cast<const float2*>(aptr);

#pragma unroll 2
    for (int mi = 0; mi < M; ++mi) {
        const float2 a = a_next;
        if (mi + 1 < M)
            a_next = *reinterpret_cast<const float2*>(aptr + (size_t)(mi + 1) * 1024);
        const ull a0 = dup2(a.x);
        const ull a1 = dup2(a.y);
        const ulonglong2* crow = reinterpret_cast<const ulonglong2*>(&cgs[mi][0]);
#pragma unroll
        for (int q = 0; q < 8; q++) {
            // One LDS.128 (broadcast) = 2 packed cg pairs = 4 r values.
            const ulonglong2 c = crow[q];
            acc[2 * q][0]     = fma2(c.x, a0, acc[2 * q][0]);
            acc[2 * q][1]     = fma2(c.x, a1, acc[2 * q][1]);
            acc[2 * q + 1][0] = fma2(c.y, a0, acc[2 * q + 1][0]);
            acc[2 * q + 1][1] = fma2(c.y, a1, acc[2 * q + 1][1]);
        }
    }

    // Epilogue: 2x2 register transpose per pair -> coalesced STG.64 per r.
#pragma unroll
    for (int p = 0; p < 16; p++) {
        float x0, y0, x1, y1;
        unpack2(acc[p][0], x0, y0);   // (b_{2p}(n0),   b_{2p+1}(n0))
        unpack2(acc[p][1], x1, y1);   // (b_{2p}(n0+1), b_{2p+1}(n0+1))
        const ull v0 = pack2(x0, x1); // b_{2p}   at n0, n0+1
        const ull v1 = pack2(y0, y1); // b_{2p+1} at n0, n0+1
        const int r0 = 2 * p;
        const int r1 = 2 * p + 1;
        if (r0 < 8) {
            *reinterpret_cast<ull*>(out0 + ((size_t)r0 * F + f) * 1024 + n0) = v0;
        } else {
            *reinterpret_cast<ull*>(out1 + ((size_t)(r0 - 8) * F + f) * 1024 + n0) = v0;
        }
        if (r1 < 8) {
            *reinterpret_cast<ull*>(out0 + ((size_t)r1 * F + f) * 1024 + n0) = v1;
        } else {
            *reinterpret_cast<ull*>(out1 + ((size_t)(r1 - 8) * F + f) * 1024 + n0) = v1;
        }
    }
}

extern "C" void kernel_launch(void* const* d_in, const int* in_sizes, int n_in,
                              void* d_out, int out_size) {
    (void)in_sizes; (void)n_in; (void)out_size;
    const float* A2_l11  = (const float*)d_in[0];   // [1024,  9, 1024]
    const float* A2_l22  = (const float*)d_in[1];   // [1024, 25, 1024]
    const float* A2_l33  = (const float*)d_in[2];   // [1024, 49, 1024]
    const float* A3_l111 = (const float*)d_in[3];   // [ 512, 27, 1024]
    const float* A3_l211 = (const float*)d_in[4];   // [ 512, 45, 1024]
    const float* CG0_0 = (const float*)d_in[5];     // [ 8,  9]
    const float* CG0_1 = (const float*)d_in[6];     // [ 8, 25]
    const float* CG0_2 = (const float*)d_in[7];     // [ 8, 49]
    const float* CG0_3 = (const float*)d_in[8];     // [ 8, 27]
    const float* CG0_4 = (const float*)d_in[9];     // [ 8, 45]
    const float* CG1_0 = (const float*)d_in[10];    // [24,  9]
    const float* CG1_1 = (const float*)d_in[11];    // [24, 25]
    const float* CG1_2 = (const float*)d_in[12];    // [24, 49]
    const float* CG1_3 = (const float*)d_in[13];    // [24, 27]
    const float* CG1_4 = (const float*)d_in[14];    // [24, 45]
    float* out = (float*)d_out;

    // Output region offsets (elements), tuple order b0(5) then b1(5):
    constexpr size_t o0_0 = 0;
    constexpr size_t o0_1 = o0_0 + (size_t)8 * 1024 * 1024;
    constexpr size_t o0_2 = o0_1 + (size_t)8 * 1024 * 1024;
    constexpr size_t o0_3 = o0_2 + (size_t)8 * 1024 * 1024;
    constexpr size_t o0_4 = o0_3 + (size_t)8 * 512 * 1024;
    constexpr size_t o1_0 = o0_4 + (size_t)8 * 512 * 1024;
    constexpr size_t o1_1 = o1_0 + (size_t)24 * 1024 * 1024;
    constexpr size_t o1_2 = o1_1 + (size_t)24 * 1024 * 1024;
    constexpr size_t o1_3 = o1_2 + (size_t)24 * 1024 * 1024;
    constexpr size_t o1_4 = o1_3 + (size_t)24 * 512 * 1024;

    const dim3 blk(256);
    sym_kernel<9, 1024><<<dim3(1024, 2), blk>>>(A2_l11,  CG0_0, CG1_0, out + o0_0, out + o1_0);
    sym_kernel<25, 1024><<<dim3(1024, 2), blk>>>(A2_l22, CG0_1, CG1_1, out + o0_1, out + o1_1);
    sym_kernel<49, 1024><<<dim3(1024, 2), blk>>>(A2_l33, CG0_2, CG1_2, out + o0_2, out + o1_2);
    sym_kernel<27, 512><<<dim3(512, 2), blk>>>(A3_l111, CG0_3, CG1_3, out + o0_3, out + o1_3);
    sym_kernel<45, 512><<<dim3(512, 2), blk>>>(A3_l211, CG0_4, CG1_4, out + o0_4, out + o1_4);
}